// round 15
// baseline (speedup 1.0000x reference)
#include <cuda_runtime.h>
#include <cuda_fp16.h>
#include <math_constants.h>
#include <cstdint>

#define Bsz 4
#define SEQ 2048
#define DMODEL 1024
#define NHEAD 16
#define HDIM 64
#define BH (Bsz * NHEAD)          // 64
#define MROWS (Bsz * SEQ)         // 8192
#define QKVN (3 * DMODEL)         // 3072

__device__ __half g_qkv[MROWS * QKVN];
__device__ __half g_att[MROWS * DMODEL];
__device__ __half g_xh[MROWS * DMODEL];
__device__ __half g_wqkv_t[QKVN * DMODEL];
__device__ __half g_wp_t[DMODEL * DMODEL];

// ---------------------------------------------------------------------------
__device__ __forceinline__ void mma_f16(
    float& d0, float& d1, float& d2, float& d3,
    uint32_t a0, uint32_t a1, uint32_t a2, uint32_t a3,
    uint32_t b0, uint32_t b1)
{
    asm volatile(
        "mma.sync.aligned.m16n8k16.row.col.f32.f16.f16.f32 "
        "{%0,%1,%2,%3}, {%4,%5,%6,%7}, {%8,%9}, {%0,%1,%2,%3};\n"
        : "+f"(d0), "+f"(d1), "+f"(d2), "+f"(d3)
        : "r"(a0), "r"(a1), "r"(a2), "r"(a3), "r"(b0), "r"(b1));
}

__device__ __forceinline__ void ldm_x4(
    uint32_t& r0, uint32_t& r1, uint32_t& r2, uint32_t& r3, uint32_t addr)
{
    asm volatile("ldmatrix.sync.aligned.m8n8.x4.shared.b16 {%0,%1,%2,%3}, [%4];"
        : "=r"(r0), "=r"(r1), "=r"(r2), "=r"(r3) : "r"(addr));
}

__device__ __forceinline__ void ldm_x4t(
    uint32_t& r0, uint32_t& r1, uint32_t& r2, uint32_t& r3, uint32_t addr)
{
    asm volatile("ldmatrix.sync.aligned.m8n8.x4.trans.shared.b16 {%0,%1,%2,%3}, [%4];"
        : "=r"(r0), "=r"(r1), "=r"(r2), "=r"(r3) : "r"(addr));
}

__device__ __forceinline__ uint32_t h2exp2(uint32_t x) {
    uint32_t r;
    asm("ex2.approx.f16x2 %0, %1;" : "=r"(r) : "r"(x));
    return r;
}

__device__ __forceinline__ void cp16(uint32_t dst, const void* src) {
    asm volatile("cp.async.cg.shared.global [%0], [%1], 16;"
                 :: "r"(dst), "l"(src) : "memory");
}
__device__ __forceinline__ void cp_commit() {
    asm volatile("cp.async.commit_group;" ::: "memory");
}
__device__ __forceinline__ void cp_wait0() {
    asm volatile("cp.async.wait_group 0;" ::: "memory");
}
__device__ __forceinline__ uint32_t smem_u32(const void* p) {
    uint32_t a;
    asm("{ .reg .u64 t; cvta.to.shared.u64 t, %1; cvt.u32.u64 %0, t; }"
        : "=r"(a) : "l"(p));
    return a;
}

// ---------------------------------------------------------------------------
// fused prepass (unchanged)
// ---------------------------------------------------------------------------
#define X2H_BLOCKS (MROWS * DMODEL / 4 / 256)            // 8192
#define WQKV_BLOCKS ((DMODEL / 32) * (QKVN / 32))        // 3072
#define WP_BLOCKS ((DMODEL / 32) * (DMODEL / 32))        // 1024
#define PRE_BLOCKS (X2H_BLOCKS + WQKV_BLOCKS + WP_BLOCKS)

__device__ __forceinline__ void transpose_tile(
    const float* __restrict__ W, __half* __restrict__ Wt,
    int K, int N, int kbi, int nbi, float (*t)[33], int tx, int ty)
{
    const int kb = kbi * 32, nb = nbi * 32;
#pragma unroll
    for (int i = 0; i < 32; i += 8)
        t[ty + i][tx] = W[(size_t)(kb + ty + i) * N + nb + tx];
    __syncthreads();
#pragma unroll
    for (int i = 0; i < 32; i += 8)
        Wt[(size_t)(nb + ty + i) * K + kb + tx] = __float2half_rn(t[tx][ty + i]);
}

__global__ __launch_bounds__(256) void prepass_kernel(
    const float* __restrict__ x, __half* __restrict__ xh,
    const float* __restrict__ Wqkv, __half* __restrict__ wqkv_t,
    const float* __restrict__ Wp, __half* __restrict__ wp_t)
{
    __shared__ float t[32][33];
    const int bid = blockIdx.x;
    const int tid = threadIdx.x;
    if (bid < X2H_BLOCKS) {
        size_t i = ((size_t)bid * 256 + tid) * 4;
        float4 v = *reinterpret_cast<const float4*>(x + i);
        __half2 h0 = __floats2half2_rn(v.x, v.y);
        __half2 h1 = __floats2half2_rn(v.z, v.w);
        *reinterpret_cast<uint2*>(xh + i) =
            make_uint2(*(uint32_t*)&h0, *(uint32_t*)&h1);
    } else if (bid < X2H_BLOCKS + WQKV_BLOCKS) {
        int tb = bid - X2H_BLOCKS;
        transpose_tile(Wqkv, wqkv_t, DMODEL, QKVN,
                       tb % (DMODEL / 32), tb / (DMODEL / 32),
                       t, tid & 31, tid >> 5);
    } else {
        int tb = bid - X2H_BLOCKS - WQKV_BLOCKS;
        transpose_tile(Wp, wp_t, DMODEL, DMODEL,
                       tb % (DMODEL / 32), tb / (DMODEL / 32),
                       t, tid & 31, tid >> 5);
    }
}

// ---------------------------------------------------------------------------
// fp16 GEMM (unchanged from R14): GKH=128, 2-stage double buffer.
// ---------------------------------------------------------------------------
#define GM 128
#define GN 256
#define GKH 128
#define ASTR_B 272
#define A_BYTES (GM * ASTR_B)
#define B_BYTES (GN * ASTR_B)
#define STAGE_BYTES (A_BYTES + B_BYTES)
#define GEMM_SMEM_BYTES (2 * STAGE_BYTES)   // 208896
#define GT 512

template <int HALF_OUT>
__global__ __launch_bounds__(GT, 1) void gemm_f16_kernel(
    const __half* __restrict__ A, const __half* __restrict__ Bt,
    const float* __restrict__ bias, void* __restrict__ Cv,
    int M, int N, int K)
{
    extern __shared__ uint32_t smw[];
    const int tid  = threadIdx.x;
    const int warp = tid >> 5;
    const int lane = tid & 31;
    const int grp  = lane >> 2;
    const int qid  = lane & 3;
    const int wm   = warp & 3;
    const int wn   = warp >> 2;
    const int rowBase = blockIdx.y * GM;
    const int colBase = blockIdx.x * GN;

    const __half* Ap = A + (size_t)rowBase * K;
    const __half* Bp = Bt + (size_t)colBase * K;
    const uint32_t sbase = smem_u32(smw);

    float acc[2][8][4];
#pragma unroll
    for (int mt = 0; mt < 2; mt++)
#pragma unroll
        for (int nt = 0; nt < 8; nt++)
#pragma unroll
            for (int v = 0; v < 4; v++) acc[mt][nt][v] = 0.f;

    const int nchunk = K / GKH;

    auto issue_stage = [&](int c) {
        const uint32_t abase = sbase + (c & 1) * STAGE_BYTES;
        const uint32_t bbase = abase + A_BYTES;
        const int k0 = c * GKH;
#pragma unroll
        for (int i = 0; i < 4; i++) {
            int id = tid + i * GT;
            int r = id >> 4, q = id & 15;
            cp16(abase + r * ASTR_B + q * 16,
                 Ap + (size_t)r * K + k0 + q * 8);
        }
#pragma unroll
        for (int i = 0; i < 8; i++) {
            int id = tid + i * GT;
            int r = id >> 4, q = id & 15;
            cp16(bbase + r * ASTR_B + q * 16,
                 Bp + (size_t)r * K + k0 + q * 8);
        }
        cp_commit();
    };

    issue_stage(0);

    const uint32_t a_off = (uint32_t)(lane & 15) * ASTR_B + (uint32_t)(lane >> 4) * 16;
    const uint32_t b_off = (uint32_t)((lane & 7) + ((lane >> 4) << 3)) * ASTR_B
                         + (uint32_t)((lane >> 3) & 1) * 16;

    for (int c = 0; c < nchunk; c++) {
        cp_wait0();
        __syncthreads();
        if (c + 1 < nchunk) issue_stage(c + 1);

        const uint32_t abase = sbase + (c & 1) * STAGE_BYTES;
        const uint32_t bbase = abase + A_BYTES;

#pragma unroll
        for (int s = 0; s < 8; s++) {
            const uint32_t kb = s * 32;
            uint32_t af[2][4];
#pragma unroll
            for (int mt = 0; mt < 2; mt++)
                ldm_x4(af[mt][0], af[mt][1], af[mt][2], af[mt][3],
                       abase + (wm * 32 + mt * 16) * ASTR_B + a_off + kb);
#pragma unroll
            for (int ntp = 0; ntp < 4; ntp++) {
                uint32_t b0, b1, b2, b3;
                ldm_x4(b0, b1, b2, b3,
                       bbase + (wn * 64 + ntp * 16) * ASTR_B + b_off + kb);
#pragma unroll
                for (int mt = 0; mt < 2; mt++) {
                    mma_f16(acc[mt][2 * ntp][0], acc[mt][2 * ntp][1],
                            acc[mt][2 * ntp][2], acc[mt][2 * ntp][3],
                            af[mt][0], af[mt][1], af[mt][2], af[mt][3], b0, b1);
                    mma_f16(acc[mt][2 * ntp + 1][0], acc[mt][2 * ntp + 1][1],
                            acc[mt][2 * ntp + 1][2], acc[mt][2 * ntp + 1][3],
                            af[mt][0], af[mt][1], af[mt][2], af[mt][3], b2, b3);
                }
            }
        }
    }

#pragma unroll
    for (int mt = 0; mt < 2; mt++) {
#pragma unroll
        for (int nt = 0; nt < 8; nt++) {
            int c = colBase + wn * 64 + nt * 8 + 2 * qid;
            float bx = bias[c], by = bias[c + 1];
            int r0 = rowBase + wm * 32 + mt * 16 + grp;
            if (HALF_OUT) {
                __half* C = (__half*)Cv;
                __half2 o0 = __floats2half2_rn(acc[mt][nt][0] + bx, acc[mt][nt][1] + by);
                *reinterpret_cast<__half2*>(C + (size_t)r0 * N + c) = o0;
                __half2 o1 = __floats2half2_rn(acc[mt][nt][2] + bx, acc[mt][nt][3] + by);
                *reinterpret_cast<__half2*>(C + (size_t)(r0 + 8) * N + c) = o1;
            } else {
                float* C = (float*)Cv;
                float2 o0 = make_float2(acc[mt][nt][0] + bx, acc[mt][nt][1] + by);
                *reinterpret_cast<float2*>(C + (size_t)r0 * N + c) = o0;
                float2 o1 = make_float2(acc[mt][nt][2] + bx, acc[mt][nt][3] + by);
                *reinterpret_cast<float2*>(C + (size_t)(r0 + 8) * N + c) = o1;
            }
        }
    }
}

// ---------------------------------------------------------------------------
// Fused flash attention: diagonal K-block peeled with per-warp trimmed bounds.
// ---------------------------------------------------------------------------
#define KS_B 176
#define KSB_SIZE (128 * KS_B)
#define PS_B 272
#define PS_W 68
#define KS0_OFF 0
#define KS1_OFF KSB_SIZE
#define VS0_OFF (2 * KSB_SIZE)
#define VS1_OFF (3 * KSB_SIZE)
#define PS_OFF  (4 * KSB_SIZE)
#define FA_SMEM_BYTES (PS_OFF + 128 * PS_B)   // 124928

#define QSCALE 0.18033688f            // 0.125 * log2(e)

__global__ __launch_bounds__(256, 1) void fa_kernel(
    const __half* __restrict__ qkv, __half* __restrict__ att)
{
    extern __shared__ uint32_t smw[];
    const uint32_t sbase = smem_u32(smw);
    const uint32_t ps_base = sbase + PS_OFF;
    uint32_t* Ps = smw + PS_OFF / 4;

    const int qb = 15 - blockIdx.x;
    const int bh = blockIdx.y;
    const int b = bh >> 4, h = bh & 15;
    const __half* Qp = qkv + (size_t)b * SEQ * QKVN + h * HDIM;
    const __half* Kp = Qp + DMODEL;
    const __half* Vp = Qp + 2 * DMODEL;

    const int tid = threadIdx.x, warp = tid >> 5, lane = tid & 31;
    const int grp = lane >> 2, qid = lane & 3;

    const uint32_t aQ_off = (uint32_t)(warp * 16 + (lane & 15)) * PS_B
                          + (uint32_t)(lane >> 4) * 16;
    const uint32_t bK_off = (uint32_t)((lane & 7) + ((lane >> 4) << 3)) * KS_B
                          + (uint32_t)((lane >> 3) & 1) * 16;
    const uint32_t aP_off = aQ_off;
    const uint32_t bVt_off = (uint32_t)((lane & 7) + (((lane >> 3) & 1) << 3)) * KS_B
                           + (uint32_t)(lane >> 4) * 16;

    auto issue_kv = [&](int kb) {
        const uint32_t kbuf = sbase + ((kb & 1) ? KS1_OFF : KS0_OFF);
        const uint32_t vbuf = sbase + ((kb & 1) ? VS1_OFF : VS0_OFF);
#pragma unroll
        for (int i = 0; i < 4; i++) {
            int id = tid + i * 256;
            int r = id >> 3, q = id & 7;
            cp16(kbuf + r * KS_B + q * 16,
                 Kp + (size_t)(kb * 128 + r) * QKVN + q * 8);
            cp16(vbuf + r * KS_B + q * 16,
                 Vp + (size_t)(kb * 128 + r) * QKVN + q * 8);
        }
        cp_commit();
    };

    issue_kv(0);

    {
        const __half2 sc = __floats2half2_rn(QSCALE, QSCALE);
#pragma unroll
        for (int i = 0; i < 4; i++) {
            int id = tid + i * 256;
            int r = id >> 3, u = id & 7;
            uint2 v = *reinterpret_cast<const uint2*>(
                Qp + (size_t)(qb * 128 + r) * QKVN + u * 8 + 0);
            uint2 w = *reinterpret_cast<const uint2*>(
                Qp + (size_t)(qb * 128 + r) * QKVN + u * 8 + 4);
            __half2 h0 = __hmul2(*(__half2*)&v.x, sc);
            __half2 h1 = __hmul2(*(__half2*)&v.y, sc);
            __half2 h2 = __hmul2(*(__half2*)&w.x, sc);
            __half2 h3 = __hmul2(*(__half2*)&w.y, sc);
            uint32_t* dst = Ps + r * PS_W + u * 4;
            dst[0] = *(uint32_t*)&h0; dst[1] = *(uint32_t*)&h1;
            dst[2] = *(uint32_t*)&h2; dst[3] = *(uint32_t*)&h3;
        }
        uint32_t* V0 = smw + VS0_OFF / 4;
        uint32_t* V1 = smw + VS1_OFF / 4;
#pragma unroll
        for (int i = 0; i < 6; i++) {
            int id = tid + i * 256;
            int r = id / 12, w = id % 12;
            uint32_t val = (w == 0) ? 0x00003C00u : 0u;
            V0[r * 44 + 32 + w] = val;
            V1[r * 44 + 32 + w] = val;
        }
    }
    __syncthreads();

    uint32_t aq[4][4];
#pragma unroll
    for (int s = 0; s < 4; s++)
        ldm_x4(aq[s][0], aq[s][1], aq[s][2], aq[s][3], ps_base + aQ_off + s * 32);

    float m0v = -CUDART_INF_F, m1v = -CUDART_INF_F;
    float acc_o[8][4];
    float acc_l[4];
#pragma unroll
    for (int j = 0; j < 8; j++)
#pragma unroll
        for (int v = 0; v < 4; v++) acc_o[j][v] = 0.f;
#pragma unroll
    for (int v = 0; v < 4; v++) acc_l[v] = 0.f;

    const int pr0 = (warp * 16 + grp) * PS_W;
    const int pr1 = pr0 + 8 * PS_W;

    // ---------------- non-diagonal K blocks (no masking) ----------------
    for (int kb = 0; kb < qb; kb++) {
        cp_wait0();
        __syncthreads();
        issue_kv(kb + 1);

        const uint32_t kbuf = sbase + ((kb & 1) ? KS1_OFF : KS0_OFF);
        const uint32_t vbuf = sbase + ((kb & 1) ? VS1_OFF : VS0_OFF);

        float s_[16][4];
#pragma unroll
        for (int nt = 0; nt < 16; nt++)
#pragma unroll
            for (int v = 0; v < 4; v++) s_[nt][v] = 0.f;
#pragma unroll
        for (int s = 0; s < 4; s++) {
#pragma unroll
            for (int ntp = 0; ntp < 8; ntp++) {
                uint32_t b0, b1, b2, b3;
                ldm_x4(b0, b1, b2, b3, kbuf + ntp * 16 * KS_B + bK_off + s * 32);
                mma_f16(s_[2 * ntp][0], s_[2 * ntp][1], s_[2 * ntp][2], s_[2 * ntp][3],
                        aq[s][0], aq[s][1], aq[s][2], aq[s][3], b0, b1);
                mma_f16(s_[2 * ntp + 1][0], s_[2 * ntp + 1][1],
                        s_[2 * ntp + 1][2], s_[2 * ntp + 1][3],
                        aq[s][0], aq[s][1], aq[s][2], aq[s][3], b2, b3);
            }
        }

        float mx0 = -CUDART_INF_F, mx1 = -CUDART_INF_F;
#pragma unroll
        for (int nt = 0; nt < 16; nt++) {
            mx0 = fmaxf(mx0, fmaxf(s_[nt][0], s_[nt][1]));
            mx1 = fmaxf(mx1, fmaxf(s_[nt][2], s_[nt][3]));
        }
        mx0 = fmaxf(mx0, __shfl_xor_sync(0xffffffffu, mx0, 1));
        mx0 = fmaxf(mx0, __shfl_xor_sync(0xffffffffu, mx0, 2));
        mx1 = fmaxf(mx1, __shfl_xor_sync(0xffffffffu, mx1, 1));
        mx1 = fmaxf(mx1, __shfl_xor_sync(0xffffffffu, mx1, 2));

        float mn0 = fmaxf(m0v, mx0), mn1 = fmaxf(m1v, mx1);
        float a0 = exp2f(m0v - mn0), a1 = exp2f(m1v - mn1);
        m0v = mn0; m1v = mn1;

#pragma unroll
        for (int nt = 0; nt < 16; nt++) {
            __half2 d0 = __floats2half2_rn(s_[nt][0] - mn0, s_[nt][1] - mn0);
            __half2 d1 = __floats2half2_rn(s_[nt][2] - mn1, s_[nt][3] - mn1);
            Ps[pr0 + nt * 4 + qid] = h2exp2(*(uint32_t*)&d0);
            Ps[pr1 + nt * 4 + qid] = h2exp2(*(uint32_t*)&d1);
        }

#pragma unroll
        for (int nt = 0; nt < 8; nt++) {
            acc_o[nt][0] *= a0; acc_o[nt][1] *= a0;
            acc_o[nt][2] *= a1; acc_o[nt][3] *= a1;
        }
        acc_l[0] *= a0; acc_l[1] *= a0;
        acc_l[2] *= a1; acc_l[3] *= a1;

#pragma unroll
        for (int s = 0; s < 8; s++) {
            uint32_t ap0, ap1, ap2, ap3;
            ldm_x4(ap0, ap1, ap2, ap3, ps_base + aP_off + s * 32);
            const uint32_t vrow = vbuf + s * 16 * KS_B + bVt_off;
#pragma unroll
            for (int ntp = 0; ntp < 4; ntp++) {
                uint32_t b0, b1, b2, b3;
                ldm_x4t(b0, b1, b2, b3, vrow + ntp * 32);
                mma_f16(acc_o[2 * ntp][0], acc_o[2 * ntp][1],
                        acc_o[2 * ntp][2], acc_o[2 * ntp][3],
                        ap0, ap1, ap2, ap3, b0, b1);
                mma_f16(acc_o[2 * ntp + 1][0], acc_o[2 * ntp + 1][1],
                        acc_o[2 * ntp + 1][2], acc_o[2 * ntp + 1][3],
                        ap0, ap1, ap2, ap3, b2, b3);
            }
            {
                uint32_t e0, e1, e2, e3;
                ldm_x4t(e0, e1, e2, e3, vrow + 128);
                mma_f16(acc_l[0], acc_l[1], acc_l[2], acc_l[3],
                        ap0, ap1, ap2, ap3, e0, e1);
            }
        }
    }

    // ---------------- diagonal K block (per-warp trimmed bounds) ----------------
    {
        cp_wait0();
        __syncthreads();

        const uint32_t kbuf = sbase + ((qb & 1) ? KS1_OFF : KS0_OFF);
        const uint32_t vbuf = sbase + ((qb & 1) ? VS1_OFF : VS0_OFF);
        const int W1 = warp + 1;        // ntp blocks / PV k-steps needed
        const int NT = 2 * W1;          // 8-col s_ tiles needed

        float s_[16][4];
#pragma unroll
        for (int nt = 0; nt < 16; nt++)
#pragma unroll
            for (int v = 0; v < 4; v++) s_[nt][v] = 0.f;

#pragma unroll
        for (int s = 0; s < 4; s++) {
            for (int ntp = 0; ntp < W1; ntp++) {
                uint32_t b0, b1, b2, b3;
                ldm_x4(b0, b1, b2, b3, kbuf + ntp * 16 * KS_B + bK_off + s * 32);
                mma_f16(s_[2 * ntp][0], s_[2 * ntp][1], s_[2 * ntp][2], s_[2 * ntp][3],
                        aq[s][0], aq[s][1], aq[s][2], aq[s][3], b0, b1);
                mma_f16(s_[2 * ntp + 1][0], s_[2 * ntp + 1][1],
                        s_[2 * ntp + 1][2], s_[2 * ntp + 1][3],
                        aq[s][0], aq[s][1], aq[s][2], aq[s][3], b2, b3);
            }
        }

        // mask within the ntp==warp block only (cols 16w..16w+15)
        {
            const int r0 = warp * 16 + grp, r1 = r0 + 8;
#pragma unroll
            for (int u = 0; u < 2; u++) {
                int nt = 2 * warp + u;
                int c = nt * 8 + 2 * qid;
                if (c > r0)     s_[nt][0] = -CUDART_INF_F;
                if (c + 1 > r0) s_[nt][1] = -CUDART_INF_F;
                if (c > r1)     s_[nt][2] = -CUDART_INF_F;
                if (c + 1 > r1) s_[nt][3] = -CUDART_INF_F;
            }
        }

        float mx0 = -CUDART_INF_F, mx1 = -CUDART_INF_F;
        for (int nt = 0; nt < NT; nt++) {
            mx0 = fmaxf(mx0, fmaxf(s_[nt][0], s_[nt][1]));
            mx1 = fmaxf(mx1, fmaxf(s_[nt][2], s_[nt][3]));
        }
        mx0 = fmaxf(mx0, __shfl_xor_sync(0xffffffffu, mx0, 1));
        mx0 = fmaxf(mx0, __shfl_xor_sync(0xffffffffu, mx0, 2));
        mx1 = fmaxf(mx1, __shfl_xor_sync(0xffffffffu, mx1, 1));
        mx1 = fmaxf(mx1, __shfl_xor_sync(0xffffffffu, mx1, 2));

        float mn0 = fmaxf(m0v, mx0), mn1 = fmaxf(m1v, mx1);
        float a0 = exp2f(m0v - mn0), a1 = exp2f(m1v - mn1);

        for (int nt = 0; nt < NT; nt++) {
            __half2 d0 = __floats2half2_rn(s_[nt][0] - mn0, s_[nt][1] - mn0);
            __half2 d1 = __floats2half2_rn(s_[nt][2] - mn1, s_[nt][3] - mn1);
            Ps[pr0 + nt * 4 + qid] = h2exp2(*(uint32_t*)&d0);
            Ps[pr1 + nt * 4 + qid] = h2exp2(*(uint32_t*)&d1);
        }

#pragma unroll
        for (int nt = 0; nt < 8; nt++) {
            acc_o[nt][0] *= a0; acc_o[nt][1] *= a0;
            acc_o[nt][2] *= a1; acc_o[nt][3] *= a1;
        }
        acc_l[0] *= a0; acc_l[1] *= a0;
        acc_l[2] *= a1; acc_l[3] *= a1;

        for (int s = 0; s < W1; s++) {
            uint32_t ap0, ap1, ap2, ap3;
            ldm_x4(ap0, ap1, ap2, ap3, ps_base + aP_off + s * 32);
            const uint32_t vrow = vbuf + s * 16 * KS_B + bVt_off;
#pragma unroll
            for (int ntp = 0; ntp < 4; ntp++) {
                uint32_t b0, b1, b2, b3;
                ldm_x4t(b0, b1, b2, b3, vrow + ntp * 32);
                mma_f16(acc_o[2 * ntp][0], acc_o[2 * ntp][1],
                        acc_o[2 * ntp][2], acc_o[2 * ntp][3],
                        ap0, ap1, ap2, ap3, b0, b1);
                mma_f16(acc_o[2 * ntp + 1][0], acc_o[2 * ntp + 1][1],
                        acc_o[2 * ntp + 1][2], acc_o[2 * ntp + 1][3],
                        ap0, ap1, ap2, ap3, b2, b3);
            }
            {
                uint32_t e0, e1, e2, e3;
                ldm_x4t(e0, e1, e2, e3, vrow + 128);
                mma_f16(acc_l[0], acc_l[1], acc_l[2], acc_l[3],
                        ap0, ap1, ap2, ap3, e0, e1);
            }
        }
    }

    float lr0 = __shfl_sync(0xffffffffu, acc_l[0], lane & 28);
    float lr1 = __shfl_sync(0xffffffffu, acc_l[2], lane & 28);
    const float inv0 = 1.f / lr0, inv1 = 1.f / lr1;
    const int r0 = qb * 128 + warp * 16 + grp;
#pragma unroll
    for (int nt = 0; nt < 8; nt++) {
        int col = h * HDIM + nt * 8 + 2 * qid;
        __half2 o0 = __floats2half2_rn(acc_o[nt][0] * inv0, acc_o[nt][1] * inv0);
        *reinterpret_cast<__half2*>(att + (size_t)(b * SEQ + r0) * DMODEL + col) = o0;
        __half2 o1 = __floats2half2_rn(acc_o[nt][2] * inv1, acc_o[nt][3] * inv1);
        *reinterpret_cast<__half2*>(att + (size_t)(b * SEQ + r0 + 8) * DMODEL + col) = o1;
    }
}

// ---------------------------------------------------------------------------
extern "C" void kernel_launch(void* const* d_in, const int* in_sizes, int n_in,
                              void* d_out, int out_size)
{
    const float* x    = (const float*)d_in[0];
    const float* Wqkv = (const float*)d_in[1];
    const float* bqkv = (const float*)d_in[2];
    const float* Wp   = (const float*)d_in[3];
    const float* bp   = (const float*)d_in[4];
    float* out = (float*)d_out;

    __half *qkv, *att, *xh, *wqkv_t, *wp_t;
    cudaGetSymbolAddress((void**)&qkv, g_qkv);
    cudaGetSymbolAddress((void**)&att, g_att);
    cudaGetSymbolAddress((void**)&xh, g_xh);
    cudaGetSymbolAddress((void**)&wqkv_t, g_wqkv_t);
    cudaGetSymbolAddress((void**)&wp_t, g_wp_t);

    cudaFuncSetAttribute(fa_kernel,
                         cudaFuncAttributeMaxDynamicSharedMemorySize, FA_SMEM_BYTES);
    cudaFuncSetAttribute(gemm_f16_kernel<1>,
                         cudaFuncAttributeMaxDynamicSharedMemorySize, GEMM_SMEM_BYTES);
    cudaFuncSetAttribute(gemm_f16_kernel<0>,
                         cudaFuncAttributeMaxDynamicSharedMemorySize, GEMM_SMEM_BYTES);

    // 0) fused prepass
    prepass_kernel<<<PRE_BLOCKS, 256>>>(x, xh, Wqkv, wqkv_t, Wp, wp_t);

    // 1) QKV = x @ Wqkv + b
    {
        dim3 grid(QKVN / GN, MROWS / GM);
        gemm_f16_kernel<1><<<grid, GT, GEMM_SMEM_BYTES>>>(xh, wqkv_t, bqkv, qkv,
                                                          MROWS, QKVN, DMODEL);
    }
    // 2) fused attention -> att
    {
        dim3 grid(SEQ / 128, BH);
        fa_kernel<<<grid, 256, FA_SMEM_BYTES>>>(qkv, att);
    }
    // 3) out = att @ Wp + bp
    {
        dim3 grid(DMODEL / GN, MROWS / GM);
        gemm_f16_kernel<0><<<grid, GT, GEMM_SMEM_BYTES>>>(att, wp_t, bp, out,
                                                          MROWS, DMODEL, DMODEL);
    }
}

// round 16
// speedup vs baseline: 1.0287x; 1.0287x over previous
#include <cuda_runtime.h>
#include <cuda_fp16.h>
#include <math_constants.h>
#include <cstdint>

#define Bsz 4
#define SEQ 2048
#define DMODEL 1024
#define NHEAD 16
#define HDIM 64
#define BH (Bsz * NHEAD)          // 64
#define MROWS (Bsz * SEQ)         // 8192
#define QKVN (3 * DMODEL)         // 3072

__device__ __half g_qkv[MROWS * QKVN];
__device__ __half g_att[MROWS * DMODEL];
__device__ __half g_xh[MROWS * DMODEL];
__device__ __half g_wqkv_t[QKVN * DMODEL];
__device__ __half g_wp_t[DMODEL * DMODEL];

// ---------------------------------------------------------------------------
__device__ __forceinline__ void mma_f16(
    float& d0, float& d1, float& d2, float& d3,
    uint32_t a0, uint32_t a1, uint32_t a2, uint32_t a3,
    uint32_t b0, uint32_t b1)
{
    asm volatile(
        "mma.sync.aligned.m16n8k16.row.col.f32.f16.f16.f32 "
        "{%0,%1,%2,%3}, {%4,%5,%6,%7}, {%8,%9}, {%0,%1,%2,%3};\n"
        : "+f"(d0), "+f"(d1), "+f"(d2), "+f"(d3)
        : "r"(a0), "r"(a1), "r"(a2), "r"(a3), "r"(b0), "r"(b1));
}

__device__ __forceinline__ void ldm_x4(
    uint32_t& r0, uint32_t& r1, uint32_t& r2, uint32_t& r3, uint32_t addr)
{
    asm volatile("ldmatrix.sync.aligned.m8n8.x4.shared.b16 {%0,%1,%2,%3}, [%4];"
        : "=r"(r0), "=r"(r1), "=r"(r2), "=r"(r3) : "r"(addr));
}

__device__ __forceinline__ void ldm_x4t(
    uint32_t& r0, uint32_t& r1, uint32_t& r2, uint32_t& r3, uint32_t addr)
{
    asm volatile("ldmatrix.sync.aligned.m8n8.x4.trans.shared.b16 {%0,%1,%2,%3}, [%4];"
        : "=r"(r0), "=r"(r1), "=r"(r2), "=r"(r3) : "r"(addr));
}

__device__ __forceinline__ uint32_t h2exp2(uint32_t x) {
    uint32_t r;
    asm("ex2.approx.f16x2 %0, %1;" : "=r"(r) : "r"(x));
    return r;
}

__device__ __forceinline__ void cp16(uint32_t dst, const void* src) {
    asm volatile("cp.async.cg.shared.global [%0], [%1], 16;"
                 :: "r"(dst), "l"(src) : "memory");
}
__device__ __forceinline__ void cp_commit() {
    asm volatile("cp.async.commit_group;" ::: "memory");
}
__device__ __forceinline__ void cp_wait0() {
    asm volatile("cp.async.wait_group 0;" ::: "memory");
}
__device__ __forceinline__ uint32_t smem_u32(const void* p) {
    uint32_t a;
    asm("{ .reg .u64 t; cvta.to.shared.u64 t, %1; cvt.u32.u64 %0, t; }"
        : "=r"(a) : "l"(p));
    return a;
}

// ---------------------------------------------------------------------------
// fused prepass (unchanged)
// ---------------------------------------------------------------------------
#define X2H_BLOCKS (MROWS * DMODEL / 4 / 256)            // 8192
#define WQKV_BLOCKS ((DMODEL / 32) * (QKVN / 32))        // 3072
#define WP_BLOCKS ((DMODEL / 32) * (DMODEL / 32))        // 1024
#define PRE_BLOCKS (X2H_BLOCKS + WQKV_BLOCKS + WP_BLOCKS)

__device__ __forceinline__ void transpose_tile(
    const float* __restrict__ W, __half* __restrict__ Wt,
    int K, int N, int kbi, int nbi, float (*t)[33], int tx, int ty)
{
    const int kb = kbi * 32, nb = nbi * 32;
#pragma unroll
    for (int i = 0; i < 32; i += 8)
        t[ty + i][tx] = W[(size_t)(kb + ty + i) * N + nb + tx];
    __syncthreads();
#pragma unroll
    for (int i = 0; i < 32; i += 8)
        Wt[(size_t)(nb + ty + i) * K + kb + tx] = __float2half_rn(t[tx][ty + i]);
}

__global__ __launch_bounds__(256) void prepass_kernel(
    const float* __restrict__ x, __half* __restrict__ xh,
    const float* __restrict__ Wqkv, __half* __restrict__ wqkv_t,
    const float* __restrict__ Wp, __half* __restrict__ wp_t)
{
    __shared__ float t[32][33];
    const int bid = blockIdx.x;
    const int tid = threadIdx.x;
    if (bid < X2H_BLOCKS) {
        size_t i = ((size_t)bid * 256 + tid) * 4;
        float4 v = *reinterpret_cast<const float4*>(x + i);
        __half2 h0 = __floats2half2_rn(v.x, v.y);
        __half2 h1 = __floats2half2_rn(v.z, v.w);
        *reinterpret_cast<uint2*>(xh + i) =
            make_uint2(*(uint32_t*)&h0, *(uint32_t*)&h1);
    } else if (bid < X2H_BLOCKS + WQKV_BLOCKS) {
        int tb = bid - X2H_BLOCKS;
        transpose_tile(Wqkv, wqkv_t, DMODEL, QKVN,
                       tb % (DMODEL / 32), tb / (DMODEL / 32),
                       t, tid & 31, tid >> 5);
    } else {
        int tb = bid - X2H_BLOCKS - WQKV_BLOCKS;
        transpose_tile(Wp, wp_t, DMODEL, DMODEL,
                       tb % (DMODEL / 32), tb / (DMODEL / 32),
                       t, tid & 31, tid >> 5);
    }
}

// ---------------------------------------------------------------------------
// fp16 GEMM (unchanged from R14): GKH=128, 2-stage double buffer.
// ---------------------------------------------------------------------------
#define GM 128
#define GN 256
#define GKH 128
#define ASTR_B 272
#define A_BYTES (GM * ASTR_B)
#define B_BYTES (GN * ASTR_B)
#define STAGE_BYTES (A_BYTES + B_BYTES)
#define GEMM_SMEM_BYTES (2 * STAGE_BYTES)   // 208896
#define GT 512

template <int HALF_OUT>
__global__ __launch_bounds__(GT, 1) void gemm_f16_kernel(
    const __half* __restrict__ A, const __half* __restrict__ Bt,
    const float* __restrict__ bias, void* __restrict__ Cv,
    int M, int N, int K)
{
    extern __shared__ uint32_t smw[];
    const int tid  = threadIdx.x;
    const int warp = tid >> 5;
    const int lane = tid & 31;
    const int grp  = lane >> 2;
    const int qid  = lane & 3;
    const int wm   = warp & 3;
    const int wn   = warp >> 2;
    const int rowBase = blockIdx.y * GM;
    const int colBase = blockIdx.x * GN;

    const __half* Ap = A + (size_t)rowBase * K;
    const __half* Bp = Bt + (size_t)colBase * K;
    const uint32_t sbase = smem_u32(smw);

    float acc[2][8][4];
#pragma unroll
    for (int mt = 0; mt < 2; mt++)
#pragma unroll
        for (int nt = 0; nt < 8; nt++)
#pragma unroll
            for (int v = 0; v < 4; v++) acc[mt][nt][v] = 0.f;

    const int nchunk = K / GKH;

    auto issue_stage = [&](int c) {
        const uint32_t abase = sbase + (c & 1) * STAGE_BYTES;
        const uint32_t bbase = abase + A_BYTES;
        const int k0 = c * GKH;
#pragma unroll
        for (int i = 0; i < 4; i++) {
            int id = tid + i * GT;
            int r = id >> 4, q = id & 15;
            cp16(abase + r * ASTR_B + q * 16,
                 Ap + (size_t)r * K + k0 + q * 8);
        }
#pragma unroll
        for (int i = 0; i < 8; i++) {
            int id = tid + i * GT;
            int r = id >> 4, q = id & 15;
            cp16(bbase + r * ASTR_B + q * 16,
                 Bp + (size_t)r * K + k0 + q * 8);
        }
        cp_commit();
    };

    issue_stage(0);

    const uint32_t a_off = (uint32_t)(lane & 15) * ASTR_B + (uint32_t)(lane >> 4) * 16;
    const uint32_t b_off = (uint32_t)((lane & 7) + ((lane >> 4) << 3)) * ASTR_B
                         + (uint32_t)((lane >> 3) & 1) * 16;

    for (int c = 0; c < nchunk; c++) {
        cp_wait0();
        __syncthreads();
        if (c + 1 < nchunk) issue_stage(c + 1);

        const uint32_t abase = sbase + (c & 1) * STAGE_BYTES;
        const uint32_t bbase = abase + A_BYTES;

#pragma unroll
        for (int s = 0; s < 8; s++) {
            const uint32_t kb = s * 32;
            uint32_t af[2][4];
#pragma unroll
            for (int mt = 0; mt < 2; mt++)
                ldm_x4(af[mt][0], af[mt][1], af[mt][2], af[mt][3],
                       abase + (wm * 32 + mt * 16) * ASTR_B + a_off + kb);
#pragma unroll
            for (int ntp = 0; ntp < 4; ntp++) {
                uint32_t b0, b1, b2, b3;
                ldm_x4(b0, b1, b2, b3,
                       bbase + (wn * 64 + ntp * 16) * ASTR_B + b_off + kb);
#pragma unroll
                for (int mt = 0; mt < 2; mt++) {
                    mma_f16(acc[mt][2 * ntp][0], acc[mt][2 * ntp][1],
                            acc[mt][2 * ntp][2], acc[mt][2 * ntp][3],
                            af[mt][0], af[mt][1], af[mt][2], af[mt][3], b0, b1);
                    mma_f16(acc[mt][2 * ntp + 1][0], acc[mt][2 * ntp + 1][1],
                            acc[mt][2 * ntp + 1][2], acc[mt][2 * ntp + 1][3],
                            af[mt][0], af[mt][1], af[mt][2], af[mt][3], b2, b3);
                }
            }
        }
    }

#pragma unroll
    for (int mt = 0; mt < 2; mt++) {
#pragma unroll
        for (int nt = 0; nt < 8; nt++) {
            int c = colBase + wn * 64 + nt * 8 + 2 * qid;
            float bx = bias[c], by = bias[c + 1];
            int r0 = rowBase + wm * 32 + mt * 16 + grp;
            if (HALF_OUT) {
                __half* C = (__half*)Cv;
                __half2 o0 = __floats2half2_rn(acc[mt][nt][0] + bx, acc[mt][nt][1] + by);
                *reinterpret_cast<__half2*>(C + (size_t)r0 * N + c) = o0;
                __half2 o1 = __floats2half2_rn(acc[mt][nt][2] + bx, acc[mt][nt][3] + by);
                *reinterpret_cast<__half2*>(C + (size_t)(r0 + 8) * N + c) = o1;
            } else {
                float* C = (float*)Cv;
                float2 o0 = make_float2(acc[mt][nt][0] + bx, acc[mt][nt][1] + by);
                *reinterpret_cast<float2*>(C + (size_t)r0 * N + c) = o0;
                float2 o1 = make_float2(acc[mt][nt][2] + bx, acc[mt][nt][3] + by);
                *reinterpret_cast<float2*>(C + (size_t)(r0 + 8) * N + c) = o1;
            }
        }
    }
}

// ---------------------------------------------------------------------------
// Fused flash attention (R14 inner structure) with paired q-blocks:
// CTA p processes qb = 15-p then qb = p  -> uniform 17 iterations per CTA.
// ---------------------------------------------------------------------------
#define KS_B 176
#define KSB_SIZE (128 * KS_B)
#define PS_B 272
#define PS_W 68
#define KS0_OFF 0
#define KS1_OFF KSB_SIZE
#define VS0_OFF (2 * KSB_SIZE)
#define VS1_OFF (3 * KSB_SIZE)
#define PS_OFF  (4 * KSB_SIZE)
#define FA_SMEM_BYTES (PS_OFF + 128 * PS_B)   // 124928

#define QSCALE 0.18033688f            // 0.125 * log2(e)

__global__ __launch_bounds__(256, 1) void fa_kernel(
    const __half* __restrict__ qkv, __half* __restrict__ att)
{
    extern __shared__ uint32_t smw[];
    const uint32_t sbase = smem_u32(smw);
    const uint32_t ps_base = sbase + PS_OFF;
    uint32_t* Ps = smw + PS_OFF / 4;

    const int bh = blockIdx.y;
    const int b = bh >> 4, h = bh & 15;
    const __half* Qp = qkv + (size_t)b * SEQ * QKVN + h * HDIM;
    const __half* Kp = Qp + DMODEL;
    const __half* Vp = Qp + 2 * DMODEL;

    const int tid = threadIdx.x, warp = tid >> 5, lane = tid & 31;
    const int grp = lane >> 2, qid = lane & 3;

    const uint32_t aQ_off = (uint32_t)(warp * 16 + (lane & 15)) * PS_B
                          + (uint32_t)(lane >> 4) * 16;
    const uint32_t bK_off = (uint32_t)((lane & 7) + ((lane >> 4) << 3)) * KS_B
                          + (uint32_t)((lane >> 3) & 1) * 16;
    const uint32_t aP_off = aQ_off;
    const uint32_t bVt_off = (uint32_t)((lane & 7) + (((lane >> 3) & 1) << 3)) * KS_B
                           + (uint32_t)(lane >> 4) * 16;

    auto issue_kv = [&](int kb) {
        const uint32_t kbuf = sbase + ((kb & 1) ? KS1_OFF : KS0_OFF);
        const uint32_t vbuf = sbase + ((kb & 1) ? VS1_OFF : VS0_OFF);
#pragma unroll
        for (int i = 0; i < 4; i++) {
            int id = tid + i * 256;
            int r = id >> 3, q = id & 7;
            cp16(kbuf + r * KS_B + q * 16,
                 Kp + (size_t)(kb * 128 + r) * QKVN + q * 8);
            cp16(vbuf + r * KS_B + q * 16,
                 Vp + (size_t)(kb * 128 + r) * QKVN + q * 8);
        }
        cp_commit();
    };

    // ones/zero columns of both V buffers: written once, never overwritten
    // by cp.async (which touches only bytes [0,128) of each 176B row).
    {
        uint32_t* V0 = smw + VS0_OFF / 4;
        uint32_t* V1 = smw + VS1_OFF / 4;
#pragma unroll
        for (int i = 0; i < 6; i++) {
            int id = tid + i * 256;
            int r = id / 12, w = id % 12;
            uint32_t val = (w == 0) ? 0x00003C00u : 0u;
            V0[r * 44 + 32 + w] = val;
            V1[r * 44 + 32 + w] = val;
        }
    }

    const int pr0 = (warp * 16 + grp) * PS_W;
    const int pr1 = pr0 + 8 * PS_W;

    for (int qi = 0; qi < 2; qi++) {
        const int qb = qi ? (int)blockIdx.x : 15 - (int)blockIdx.x;

        // All warps done with previous q-block's smem (Ps reads in PV,
        // K/V buffer reads) before restaging. Also orders ones-init.
        __syncthreads();
        issue_kv(0);

        // ---- stage Q (scaled) into Ps ----
        {
            const __half2 sc = __floats2half2_rn(QSCALE, QSCALE);
#pragma unroll
            for (int i = 0; i < 4; i++) {
                int id = tid + i * 256;
                int r = id >> 3, u = id & 7;
                uint2 v = *reinterpret_cast<const uint2*>(
                    Qp + (size_t)(qb * 128 + r) * QKVN + u * 8 + 0);
                uint2 w = *reinterpret_cast<const uint2*>(
                    Qp + (size_t)(qb * 128 + r) * QKVN + u * 8 + 4);
                __half2 h0 = __hmul2(*(__half2*)&v.x, sc);
                __half2 h1 = __hmul2(*(__half2*)&v.y, sc);
                __half2 h2 = __hmul2(*(__half2*)&w.x, sc);
                __half2 h3 = __hmul2(*(__half2*)&w.y, sc);
                uint32_t* dst = Ps + r * PS_W + u * 4;
                dst[0] = *(uint32_t*)&h0; dst[1] = *(uint32_t*)&h1;
                dst[2] = *(uint32_t*)&h2; dst[3] = *(uint32_t*)&h3;
            }
        }
        __syncthreads();

        uint32_t aq[4][4];
#pragma unroll
        for (int s = 0; s < 4; s++)
            ldm_x4(aq[s][0], aq[s][1], aq[s][2], aq[s][3], ps_base + aQ_off + s * 32);

        float m0v = -CUDART_INF_F, m1v = -CUDART_INF_F;
        float acc_o[8][4];
        float acc_l[4];
#pragma unroll
        for (int j = 0; j < 8; j++)
#pragma unroll
            for (int v = 0; v < 4; v++) acc_o[j][v] = 0.f;
#pragma unroll
        for (int v = 0; v < 4; v++) acc_l[v] = 0.f;

        for (int kb = 0; kb <= qb; kb++) {
            cp_wait0();
            __syncthreads();
            if (kb < qb) issue_kv(kb + 1);

            const uint32_t kbuf = sbase + ((kb & 1) ? KS1_OFF : KS0_OFF);
            const uint32_t vbuf = sbase + ((kb & 1) ? VS1_OFF : VS0_OFF);

            float s_[16][4];
#pragma unroll
            for (int nt = 0; nt < 16; nt++)
#pragma unroll
                for (int v = 0; v < 4; v++) s_[nt][v] = 0.f;
#pragma unroll
            for (int s = 0; s < 4; s++) {
#pragma unroll
                for (int ntp = 0; ntp < 8; ntp++) {
                    uint32_t b0, b1, b2, b3;
                    ldm_x4(b0, b1, b2, b3, kbuf + ntp * 16 * KS_B + bK_off + s * 32);
                    mma_f16(s_[2 * ntp][0], s_[2 * ntp][1], s_[2 * ntp][2], s_[2 * ntp][3],
                            aq[s][0], aq[s][1], aq[s][2], aq[s][3], b0, b1);
                    mma_f16(s_[2 * ntp + 1][0], s_[2 * ntp + 1][1],
                            s_[2 * ntp + 1][2], s_[2 * ntp + 1][3],
                            aq[s][0], aq[s][1], aq[s][2], aq[s][3], b2, b3);
                }
            }

            if (kb == qb) {
                const int r0 = warp * 16 + grp, r1 = r0 + 8;
#pragma unroll
                for (int nt = 0; nt < 16; nt++) {
                    int c = nt * 8 + 2 * qid;
                    if (c > r0)     s_[nt][0] = -CUDART_INF_F;
                    if (c + 1 > r0) s_[nt][1] = -CUDART_INF_F;
                    if (c > r1)     s_[nt][2] = -CUDART_INF_F;
                    if (c + 1 > r1) s_[nt][3] = -CUDART_INF_F;
                }
            }

            float mx0 = -CUDART_INF_F, mx1 = -CUDART_INF_F;
#pragma unroll
            for (int nt = 0; nt < 16; nt++) {
                mx0 = fmaxf(mx0, fmaxf(s_[nt][0], s_[nt][1]));
                mx1 = fmaxf(mx1, fmaxf(s_[nt][2], s_[nt][3]));
            }
            mx0 = fmaxf(mx0, __shfl_xor_sync(0xffffffffu, mx0, 1));
            mx0 = fmaxf(mx0, __shfl_xor_sync(0xffffffffu, mx0, 2));
            mx1 = fmaxf(mx1, __shfl_xor_sync(0xffffffffu, mx1, 1));
            mx1 = fmaxf(mx1, __shfl_xor_sync(0xffffffffu, mx1, 2));

            float mn0 = fmaxf(m0v, mx0), mn1 = fmaxf(m1v, mx1);
            float a0 = exp2f(m0v - mn0), a1 = exp2f(m1v - mn1);
            m0v = mn0; m1v = mn1;

#pragma unroll
            for (int nt = 0; nt < 16; nt++) {
                __half2 d0 = __floats2half2_rn(s_[nt][0] - mn0, s_[nt][1] - mn0);
                __half2 d1 = __floats2half2_rn(s_[nt][2] - mn1, s_[nt][3] - mn1);
                Ps[pr0 + nt * 4 + qid] = h2exp2(*(uint32_t*)&d0);
                Ps[pr1 + nt * 4 + qid] = h2exp2(*(uint32_t*)&d1);
            }

#pragma unroll
            for (int nt = 0; nt < 8; nt++) {
                acc_o[nt][0] *= a0; acc_o[nt][1] *= a0;
                acc_o[nt][2] *= a1; acc_o[nt][3] *= a1;
            }
            acc_l[0] *= a0; acc_l[1] *= a0;
            acc_l[2] *= a1; acc_l[3] *= a1;

#pragma unroll
            for (int s = 0; s < 8; s++) {
                uint32_t ap0, ap1, ap2, ap3;
                ldm_x4(ap0, ap1, ap2, ap3, ps_base + aP_off + s * 32);
                const uint32_t vrow = vbuf + s * 16 * KS_B + bVt_off;
#pragma unroll
                for (int ntp = 0; ntp < 4; ntp++) {
                    uint32_t b0, b1, b2, b3;
                    ldm_x4t(b0, b1, b2, b3, vrow + ntp * 32);
                    mma_f16(acc_o[2 * ntp][0], acc_o[2 * ntp][1],
                            acc_o[2 * ntp][2], acc_o[2 * ntp][3],
                            ap0, ap1, ap2, ap3, b0, b1);
                    mma_f16(acc_o[2 * ntp + 1][0], acc_o[2 * ntp + 1][1],
                            acc_o[2 * ntp + 1][2], acc_o[2 * ntp + 1][3],
                            ap0, ap1, ap2, ap3, b2, b3);
                }
                {
                    uint32_t e0, e1, e2, e3;
                    ldm_x4t(e0, e1, e2, e3, vrow + 128);
                    mma_f16(acc_l[0], acc_l[1], acc_l[2], acc_l[3],
                            ap0, ap1, ap2, ap3, e0, e1);
                }
            }
        }

        // ---- epilogue for this q-block ----
        float lr0 = __shfl_sync(0xffffffffu, acc_l[0], lane & 28);
        float lr1 = __shfl_sync(0xffffffffu, acc_l[2], lane & 28);
        const float inv0 = 1.f / lr0, inv1 = 1.f / lr1;
        const int r0 = qb * 128 + warp * 16 + grp;
#pragma unroll
        for (int nt = 0; nt < 8; nt++) {
            int col = h * HDIM + nt * 8 + 2 * qid;
            __half2 o0 = __floats2half2_rn(acc_o[nt][0] * inv0, acc_o[nt][1] * inv0);
            *reinterpret_cast<__half2*>(att + (size_t)(b * SEQ + r0) * DMODEL + col) = o0;
            __half2 o1 = __floats2half2_rn(acc_o[nt][2] * inv1, acc_o[nt][3] * inv1);
            *reinterpret_cast<__half2*>(att + (size_t)(b * SEQ + r0 + 8) * DMODEL + col) = o1;
        }
    }
}

// ---------------------------------------------------------------------------
extern "C" void kernel_launch(void* const* d_in, const int* in_sizes, int n_in,
                              void* d_out, int out_size)
{
    const float* x    = (const float*)d_in[0];
    const float* Wqkv = (const float*)d_in[1];
    const float* bqkv = (const float*)d_in[2];
    const float* Wp   = (const float*)d_in[3];
    const float* bp   = (const float*)d_in[4];
    float* out = (float*)d_out;

    __half *qkv, *att, *xh, *wqkv_t, *wp_t;
    cudaGetSymbolAddress((void**)&qkv, g_qkv);
    cudaGetSymbolAddress((void**)&att, g_att);
    cudaGetSymbolAddress((void**)&xh, g_xh);
    cudaGetSymbolAddress((void**)&wqkv_t, g_wqkv_t);
    cudaGetSymbolAddress((void**)&wp_t, g_wp_t);

    cudaFuncSetAttribute(fa_kernel,
                         cudaFuncAttributeMaxDynamicSharedMemorySize, FA_SMEM_BYTES);
    cudaFuncSetAttribute(gemm_f16_kernel<1>,
                         cudaFuncAttributeMaxDynamicSharedMemorySize, GEMM_SMEM_BYTES);
    cudaFuncSetAttribute(gemm_f16_kernel<0>,
                         cudaFuncAttributeMaxDynamicSharedMemorySize, GEMM_SMEM_BYTES);

    // 0) fused prepass
    prepass_kernel<<<PRE_BLOCKS, 256>>>(x, xh, Wqkv, wqkv_t, Wp, wp_t);

    // 1) QKV = x @ Wqkv + b
    {
        dim3 grid(QKVN / GN, MROWS / GM);
        gemm_f16_kernel<1><<<grid, GT, GEMM_SMEM_BYTES>>>(xh, wqkv_t, bqkv, qkv,
                                                          MROWS, QKVN, DMODEL);
    }
    // 2) fused attention -> att (paired q-blocks: uniform load)
    {
        dim3 grid(8, BH);
        fa_kernel<<<grid, 256, FA_SMEM_BYTES>>>(qkv, att);
    }
    // 3) out = att @ Wp + bp
    {
        dim3 grid(DMODEL / GN, MROWS / GM);
        gemm_f16_kernel<0><<<grid, GT, GEMM_SMEM_BYTES>>>(att, wp_t, bp, out,
                                                          MROWS, DMODEL, DMODEL);
    }
}

// round 17
// speedup vs baseline: 1.0633x; 1.0337x over previous
#include <cuda_runtime.h>
#include <cuda_fp16.h>
#include <math_constants.h>
#include <cstdint>

#define Bsz 4
#define SEQ 2048
#define DMODEL 1024
#define NHEAD 16
#define HDIM 64
#define BH (Bsz * NHEAD)          // 64
#define MROWS (Bsz * SEQ)         // 8192
#define QKVN (3 * DMODEL)         // 3072

__device__ __half g_qkv[MROWS * QKVN];
__device__ __half g_att[MROWS * DMODEL];
__device__ __half g_xh[MROWS * DMODEL];
__device__ __half g_wqkv_t[QKVN * DMODEL];
__device__ __half g_wp_t[DMODEL * DMODEL];

// ---------------------------------------------------------------------------
__device__ __forceinline__ void mma_f16(
    float& d0, float& d1, float& d2, float& d3,
    uint32_t a0, uint32_t a1, uint32_t a2, uint32_t a3,
    uint32_t b0, uint32_t b1)
{
    asm volatile(
        "mma.sync.aligned.m16n8k16.row.col.f32.f16.f16.f32 "
        "{%0,%1,%2,%3}, {%4,%5,%6,%7}, {%8,%9}, {%0,%1,%2,%3};\n"
        : "+f"(d0), "+f"(d1), "+f"(d2), "+f"(d3)
        : "r"(a0), "r"(a1), "r"(a2), "r"(a3), "r"(b0), "r"(b1));
}

__device__ __forceinline__ void ldm_x4(
    uint32_t& r0, uint32_t& r1, uint32_t& r2, uint32_t& r3, uint32_t addr)
{
    asm volatile("ldmatrix.sync.aligned.m8n8.x4.shared.b16 {%0,%1,%2,%3}, [%4];"
        : "=r"(r0), "=r"(r1), "=r"(r2), "=r"(r3) : "r"(addr));
}

__device__ __forceinline__ void ldm_x4t(
    uint32_t& r0, uint32_t& r1, uint32_t& r2, uint32_t& r3, uint32_t addr)
{
    asm volatile("ldmatrix.sync.aligned.m8n8.x4.trans.shared.b16 {%0,%1,%2,%3}, [%4];"
        : "=r"(r0), "=r"(r1), "=r"(r2), "=r"(r3) : "r"(addr));
}

__device__ __forceinline__ uint32_t h2exp2(uint32_t x) {
    uint32_t r;
    asm("ex2.approx.f16x2 %0, %1;" : "=r"(r) : "r"(x));
    return r;
}

__device__ __forceinline__ void cp16(uint32_t dst, const void* src) {
    asm volatile("cp.async.cg.shared.global [%0], [%1], 16;"
                 :: "r"(dst), "l"(src) : "memory");
}
__device__ __forceinline__ void cp_commit() {
    asm volatile("cp.async.commit_group;" ::: "memory");
}
__device__ __forceinline__ void cp_wait0() {
    asm volatile("cp.async.wait_group 0;" ::: "memory");
}
__device__ __forceinline__ uint32_t smem_u32(const void* p) {
    uint32_t a;
    asm("{ .reg .u64 t; cvta.to.shared.u64 t, %1; cvt.u32.u64 %0, t; }"
        : "=r"(a) : "l"(p));
    return a;
}

// ---------------------------------------------------------------------------
// fused prepass (unchanged)
// ---------------------------------------------------------------------------
#define X2H_BLOCKS (MROWS * DMODEL / 4 / 256)            // 8192
#define WQKV_BLOCKS ((DMODEL / 32) * (QKVN / 32))        // 3072
#define WP_BLOCKS ((DMODEL / 32) * (DMODEL / 32))        // 1024
#define PRE_BLOCKS (X2H_BLOCKS + WQKV_BLOCKS + WP_BLOCKS)

__device__ __forceinline__ void transpose_tile(
    const float* __restrict__ W, __half* __restrict__ Wt,
    int K, int N, int kbi, int nbi, float (*t)[33], int tx, int ty)
{
    const int kb = kbi * 32, nb = nbi * 32;
#pragma unroll
    for (int i = 0; i < 32; i += 8)
        t[ty + i][tx] = W[(size_t)(kb + ty + i) * N + nb + tx];
    __syncthreads();
#pragma unroll
    for (int i = 0; i < 32; i += 8)
        Wt[(size_t)(nb + ty + i) * K + kb + tx] = __float2half_rn(t[tx][ty + i]);
}

__global__ __launch_bounds__(256) void prepass_kernel(
    const float* __restrict__ x, __half* __restrict__ xh,
    const float* __restrict__ Wqkv, __half* __restrict__ wqkv_t,
    const float* __restrict__ Wp, __half* __restrict__ wp_t)
{
    __shared__ float t[32][33];
    const int bid = blockIdx.x;
    const int tid = threadIdx.x;
    if (bid < X2H_BLOCKS) {
        size_t i = ((size_t)bid * 256 + tid) * 4;
        float4 v = *reinterpret_cast<const float4*>(x + i);
        __half2 h0 = __floats2half2_rn(v.x, v.y);
        __half2 h1 = __floats2half2_rn(v.z, v.w);
        *reinterpret_cast<uint2*>(xh + i) =
            make_uint2(*(uint32_t*)&h0, *(uint32_t*)&h1);
    } else if (bid < X2H_BLOCKS + WQKV_BLOCKS) {
        int tb = bid - X2H_BLOCKS;
        transpose_tile(Wqkv, wqkv_t, DMODEL, QKVN,
                       tb % (DMODEL / 32), tb / (DMODEL / 32),
                       t, tid & 31, tid >> 5);
    } else {
        int tb = bid - X2H_BLOCKS - WQKV_BLOCKS;
        transpose_tile(Wp, wp_t, DMODEL, DMODEL,
                       tb % (DMODEL / 32), tb / (DMODEL / 32),
                       t, tid & 31, tid >> 5);
    }
}

// ---------------------------------------------------------------------------
// fp16 GEMM (unchanged from R14): GKH=128, 2-stage double buffer.
// ---------------------------------------------------------------------------
#define GM 128
#define GN 256
#define GKH 128
#define ASTR_B 272
#define A_BYTES (GM * ASTR_B)
#define B_BYTES (GN * ASTR_B)
#define STAGE_BYTES (A_BYTES + B_BYTES)
#define GEMM_SMEM_BYTES (2 * STAGE_BYTES)   // 208896
#define GT 512

template <int HALF_OUT>
__global__ __launch_bounds__(GT, 1) void gemm_f16_kernel(
    const __half* __restrict__ A, const __half* __restrict__ Bt,
    const float* __restrict__ bias, void* __restrict__ Cv,
    int M, int N, int K)
{
    extern __shared__ uint32_t smw[];
    const int tid  = threadIdx.x;
    const int warp = tid >> 5;
    const int lane = tid & 31;
    const int grp  = lane >> 2;
    const int qid  = lane & 3;
    const int wm   = warp & 3;
    const int wn   = warp >> 2;
    const int rowBase = blockIdx.y * GM;
    const int colBase = blockIdx.x * GN;

    const __half* Ap = A + (size_t)rowBase * K;
    const __half* Bp = Bt + (size_t)colBase * K;
    const uint32_t sbase = smem_u32(smw);

    float acc[2][8][4];
#pragma unroll
    for (int mt = 0; mt < 2; mt++)
#pragma unroll
        for (int nt = 0; nt < 8; nt++)
#pragma unroll
            for (int v = 0; v < 4; v++) acc[mt][nt][v] = 0.f;

    const int nchunk = K / GKH;

    auto issue_stage = [&](int c) {
        const uint32_t abase = sbase + (c & 1) * STAGE_BYTES;
        const uint32_t bbase = abase + A_BYTES;
        const int k0 = c * GKH;
#pragma unroll
        for (int i = 0; i < 4; i++) {
            int id = tid + i * GT;
            int r = id >> 4, q = id & 15;
            cp16(abase + r * ASTR_B + q * 16,
                 Ap + (size_t)r * K + k0 + q * 8);
        }
#pragma unroll
        for (int i = 0; i < 8; i++) {
            int id = tid + i * GT;
            int r = id >> 4, q = id & 15;
            cp16(bbase + r * ASTR_B + q * 16,
                 Bp + (size_t)r * K + k0 + q * 8);
        }
        cp_commit();
    };

    issue_stage(0);

    const uint32_t a_off = (uint32_t)(lane & 15) * ASTR_B + (uint32_t)(lane >> 4) * 16;
    const uint32_t b_off = (uint32_t)((lane & 7) + ((lane >> 4) << 3)) * ASTR_B
                         + (uint32_t)((lane >> 3) & 1) * 16;

    for (int c = 0; c < nchunk; c++) {
        cp_wait0();
        __syncthreads();
        if (c + 1 < nchunk) issue_stage(c + 1);

        const uint32_t abase = sbase + (c & 1) * STAGE_BYTES;
        const uint32_t bbase = abase + A_BYTES;

#pragma unroll
        for (int s = 0; s < 8; s++) {
            const uint32_t kb = s * 32;
            uint32_t af[2][4];
#pragma unroll
            for (int mt = 0; mt < 2; mt++)
                ldm_x4(af[mt][0], af[mt][1], af[mt][2], af[mt][3],
                       abase + (wm * 32 + mt * 16) * ASTR_B + a_off + kb);
#pragma unroll
            for (int ntp = 0; ntp < 4; ntp++) {
                uint32_t b0, b1, b2, b3;
                ldm_x4(b0, b1, b2, b3,
                       bbase + (wn * 64 + ntp * 16) * ASTR_B + b_off + kb);
#pragma unroll
                for (int mt = 0; mt < 2; mt++) {
                    mma_f16(acc[mt][2 * ntp][0], acc[mt][2 * ntp][1],
                            acc[mt][2 * ntp][2], acc[mt][2 * ntp][3],
                            af[mt][0], af[mt][1], af[mt][2], af[mt][3], b0, b1);
                    mma_f16(acc[mt][2 * ntp + 1][0], acc[mt][2 * ntp + 1][1],
                            acc[mt][2 * ntp + 1][2], acc[mt][2 * ntp + 1][3],
                            af[mt][0], af[mt][1], af[mt][2], af[mt][3], b2, b3);
                }
            }
        }
    }

#pragma unroll
    for (int mt = 0; mt < 2; mt++) {
#pragma unroll
        for (int nt = 0; nt < 8; nt++) {
            int c = colBase + wn * 64 + nt * 8 + 2 * qid;
            float bx = bias[c], by = bias[c + 1];
            int r0 = rowBase + wm * 32 + mt * 16 + grp;
            if (HALF_OUT) {
                __half* C = (__half*)Cv;
                __half2 o0 = __floats2half2_rn(acc[mt][nt][0] + bx, acc[mt][nt][1] + by);
                *reinterpret_cast<__half2*>(C + (size_t)r0 * N + c) = o0;
                __half2 o1 = __floats2half2_rn(acc[mt][nt][2] + bx, acc[mt][nt][3] + by);
                *reinterpret_cast<__half2*>(C + (size_t)(r0 + 8) * N + c) = o1;
            } else {
                float* C = (float*)Cv;
                float2 o0 = make_float2(acc[mt][nt][0] + bx, acc[mt][nt][1] + by);
                *reinterpret_cast<float2*>(C + (size_t)r0 * N + c) = o0;
                float2 o1 = make_float2(acc[mt][nt][2] + bx, acc[mt][nt][3] + by);
                *reinterpret_cast<float2*>(C + (size_t)(r0 + 8) * N + c) = o1;
            }
        }
    }
}

// ---------------------------------------------------------------------------
// Fused flash attention: R14 schedule (1024 CTAs, longest-first), K/V rows
// shrunk to 144B (128 data + 16 pad holding the ones-column) -> smem
// 108544B -> 2 CTAs/SM.
// ---------------------------------------------------------------------------
#define KS_B 144
#define KS_W 36
#define KSB_SIZE (128 * KS_B)                 // 18432
#define PS_B 272
#define PS_W 68
#define KS0_OFF 0
#define KS1_OFF KSB_SIZE
#define VS0_OFF (2 * KSB_SIZE)
#define VS1_OFF (3 * KSB_SIZE)
#define PS_OFF  (4 * KSB_SIZE)                // 73728
#define FA_SMEM_BYTES (PS_OFF + 128 * PS_B)   // 108544

#define QSCALE 0.18033688f            // 0.125 * log2(e)

__global__ __launch_bounds__(256, 2) void fa_kernel(
    const __half* __restrict__ qkv, __half* __restrict__ att)
{
    extern __shared__ uint32_t smw[];
    const uint32_t sbase = smem_u32(smw);
    const uint32_t ps_base = sbase + PS_OFF;
    uint32_t* Ps = smw + PS_OFF / 4;

    const int qb = 15 - blockIdx.x;
    const int bh = blockIdx.y;
    const int b = bh >> 4, h = bh & 15;
    const __half* Qp = qkv + (size_t)b * SEQ * QKVN + h * HDIM;
    const __half* Kp = Qp + DMODEL;
    const __half* Vp = Qp + 2 * DMODEL;

    const int tid = threadIdx.x, warp = tid >> 5, lane = tid & 31;
    const int grp = lane >> 2, qid = lane & 3;

    const uint32_t aQ_off = (uint32_t)(warp * 16 + (lane & 15)) * PS_B
                          + (uint32_t)(lane >> 4) * 16;
    const uint32_t bK_off = (uint32_t)((lane & 7) + ((lane >> 4) << 3)) * KS_B
                          + (uint32_t)((lane >> 3) & 1) * 16;
    const uint32_t aP_off = aQ_off;
    const uint32_t bVt_off = (uint32_t)((lane & 7) + (((lane >> 3) & 1) << 3)) * KS_B
                           + (uint32_t)(lane >> 4) * 16;

    auto issue_kv = [&](int kb) {
        const uint32_t kbuf = sbase + ((kb & 1) ? KS1_OFF : KS0_OFF);
        const uint32_t vbuf = sbase + ((kb & 1) ? VS1_OFF : VS0_OFF);
#pragma unroll
        for (int i = 0; i < 4; i++) {
            int id = tid + i * 256;
            int r = id >> 3, q = id & 7;
            cp16(kbuf + r * KS_B + q * 16,
                 Kp + (size_t)(kb * 128 + r) * QKVN + q * 8);
            cp16(vbuf + r * KS_B + q * 16,
                 Vp + (size_t)(kb * 128 + r) * QKVN + q * 8);
        }
        cp_commit();
    };

    issue_kv(0);

    {
        const __half2 sc = __floats2half2_rn(QSCALE, QSCALE);
#pragma unroll
        for (int i = 0; i < 4; i++) {
            int id = tid + i * 256;
            int r = id >> 3, u = id & 7;
            uint2 v = *reinterpret_cast<const uint2*>(
                Qp + (size_t)(qb * 128 + r) * QKVN + u * 8 + 0);
            uint2 w = *reinterpret_cast<const uint2*>(
                Qp + (size_t)(qb * 128 + r) * QKVN + u * 8 + 4);
            __half2 h0 = __hmul2(*(__half2*)&v.x, sc);
            __half2 h1 = __hmul2(*(__half2*)&v.y, sc);
            __half2 h2 = __hmul2(*(__half2*)&w.x, sc);
            __half2 h3 = __hmul2(*(__half2*)&w.y, sc);
            uint32_t* dst = Ps + r * PS_W + u * 4;
            dst[0] = *(uint32_t*)&h0; dst[1] = *(uint32_t*)&h1;
            dst[2] = *(uint32_t*)&h2; dst[3] = *(uint32_t*)&h3;
        }
        // V pad words (16B per row): col 64 = 1.0 (rowsum column), 65..71 = 0.
        // cp.async only writes bytes [0,128) of each 144B row, so these persist.
        uint32_t* V0 = smw + VS0_OFF / 4;
        uint32_t* V1 = smw + VS1_OFF / 4;
#pragma unroll
        for (int i = 0; i < 2; i++) {
            int id = tid + i * 256;        // 0..511
            int r = id >> 2, w = id & 3;   // 128 rows x 4 words
            uint32_t val = (w == 0) ? 0x00003C00u : 0u;
            V0[r * KS_W + 32 + w] = val;
            V1[r * KS_W + 32 + w] = val;
        }
    }
    __syncthreads();

    uint32_t aq[4][4];
#pragma unroll
    for (int s = 0; s < 4; s++)
        ldm_x4(aq[s][0], aq[s][1], aq[s][2], aq[s][3], ps_base + aQ_off + s * 32);

    float m0v = -CUDART_INF_F, m1v = -CUDART_INF_F;
    float acc_o[8][4];
    float acc_l[4];
#pragma unroll
    for (int j = 0; j < 8; j++)
#pragma unroll
        for (int v = 0; v < 4; v++) acc_o[j][v] = 0.f;
#pragma unroll
    for (int v = 0; v < 4; v++) acc_l[v] = 0.f;

    const int pr0 = (warp * 16 + grp) * PS_W;
    const int pr1 = pr0 + 8 * PS_W;

    for (int kb = 0; kb <= qb; kb++) {
        cp_wait0();
        __syncthreads();
        if (kb < qb) issue_kv(kb + 1);

        const uint32_t kbuf = sbase + ((kb & 1) ? KS1_OFF : KS0_OFF);
        const uint32_t vbuf = sbase + ((kb & 1) ? VS1_OFF : VS0_OFF);

        float s_[16][4];
#pragma unroll
        for (int nt = 0; nt < 16; nt++)
#pragma unroll
            for (int v = 0; v < 4; v++) s_[nt][v] = 0.f;
#pragma unroll
        for (int s = 0; s < 4; s++) {
#pragma unroll
            for (int ntp = 0; ntp < 8; ntp++) {
                uint32_t b0, b1, b2, b3;
                ldm_x4(b0, b1, b2, b3, kbuf + ntp * 16 * KS_B + bK_off + s * 32);
                mma_f16(s_[2 * ntp][0], s_[2 * ntp][1], s_[2 * ntp][2], s_[2 * ntp][3],
                        aq[s][0], aq[s][1], aq[s][2], aq[s][3], b0, b1);
                mma_f16(s_[2 * ntp + 1][0], s_[2 * ntp + 1][1],
                        s_[2 * ntp + 1][2], s_[2 * ntp + 1][3],
                        aq[s][0], aq[s][1], aq[s][2], aq[s][3], b2, b3);
            }
        }

        if (kb == qb) {
            const int r0 = warp * 16 + grp, r1 = r0 + 8;
#pragma unroll
            for (int nt = 0; nt < 16; nt++) {
                int c = nt * 8 + 2 * qid;
                if (c > r0)     s_[nt][0] = -CUDART_INF_F;
                if (c + 1 > r0) s_[nt][1] = -CUDART_INF_F;
                if (c > r1)     s_[nt][2] = -CUDART_INF_F;
                if (c + 1 > r1) s_[nt][3] = -CUDART_INF_F;
            }
        }

        float mx0 = -CUDART_INF_F, mx1 = -CUDART_INF_F;
#pragma unroll
        for (int nt = 0; nt < 16; nt++) {
            mx0 = fmaxf(mx0, fmaxf(s_[nt][0], s_[nt][1]));
            mx1 = fmaxf(mx1, fmaxf(s_[nt][2], s_[nt][3]));
        }
        mx0 = fmaxf(mx0, __shfl_xor_sync(0xffffffffu, mx0, 1));
        mx0 = fmaxf(mx0, __shfl_xor_sync(0xffffffffu, mx0, 2));
        mx1 = fmaxf(mx1, __shfl_xor_sync(0xffffffffu, mx1, 1));
        mx1 = fmaxf(mx1, __shfl_xor_sync(0xffffffffu, mx1, 2));

        float mn0 = fmaxf(m0v, mx0), mn1 = fmaxf(m1v, mx1);
        float a0 = exp2f(m0v - mn0), a1 = exp2f(m1v - mn1);
        m0v = mn0; m1v = mn1;

#pragma unroll
        for (int nt = 0; nt < 16; nt++) {
            __half2 d0 = __floats2half2_rn(s_[nt][0] - mn0, s_[nt][1] - mn0);
            __half2 d1 = __floats2half2_rn(s_[nt][2] - mn1, s_[nt][3] - mn1);
            Ps[pr0 + nt * 4 + qid] = h2exp2(*(uint32_t*)&d0);
            Ps[pr1 + nt * 4 + qid] = h2exp2(*(uint32_t*)&d1);
        }

#pragma unroll
        for (int nt = 0; nt < 8; nt++) {
            acc_o[nt][0] *= a0; acc_o[nt][1] *= a0;
            acc_o[nt][2] *= a1; acc_o[nt][3] *= a1;
        }
        acc_l[0] *= a0; acc_l[1] *= a0;
        acc_l[2] *= a1; acc_l[3] *= a1;

#pragma unroll
        for (int s = 0; s < 8; s++) {
            uint32_t ap0, ap1, ap2, ap3;
            ldm_x4(ap0, ap1, ap2, ap3, ps_base + aP_off + s * 32);
            const uint32_t vrow = vbuf + s * 16 * KS_B + bVt_off;
#pragma unroll
            for (int ntp = 0; ntp < 4; ntp++) {
                uint32_t b0, b1, b2, b3;
                ldm_x4t(b0, b1, b2, b3, vrow + ntp * 32);
                mma_f16(acc_o[2 * ntp][0], acc_o[2 * ntp][1],
                        acc_o[2 * ntp][2], acc_o[2 * ntp][3],
                        ap0, ap1, ap2, ap3, b0, b1);
                mma_f16(acc_o[2 * ntp + 1][0], acc_o[2 * ntp + 1][1],
                        acc_o[2 * ntp + 1][2], acc_o[2 * ntp + 1][3],
                        ap0, ap1, ap2, ap3, b2, b3);
            }
            {
                uint32_t e0, e1, e2, e3;
                ldm_x4t(e0, e1, e2, e3, vrow + 128);
                mma_f16(acc_l[0], acc_l[1], acc_l[2], acc_l[3],
                        ap0, ap1, ap2, ap3, e0, e1);
            }
        }
    }

    float lr0 = __shfl_sync(0xffffffffu, acc_l[0], lane & 28);
    float lr1 = __shfl_sync(0xffffffffu, acc_l[2], lane & 28);
    const float inv0 = 1.f / lr0, inv1 = 1.f / lr1;
    const int r0 = qb * 128 + warp * 16 + grp;
#pragma unroll
    for (int nt = 0; nt < 8; nt++) {
        int col = h * HDIM + nt * 8 + 2 * qid;
        __half2 o0 = __floats2half2_rn(acc_o[nt][0] * inv0, acc_o[nt][1] * inv0);
        *reinterpret_cast<__half2*>(att + (size_t)(b * SEQ + r0) * DMODEL + col) = o0;
        __half2 o1 = __floats2half2_rn(acc_o[nt][2] * inv1, acc_o[nt][3] * inv1);
        *reinterpret_cast<__half2*>(att + (size_t)(b * SEQ + r0 + 8) * DMODEL + col) = o1;
    }
}

// ---------------------------------------------------------------------------
extern "C" void kernel_launch(void* const* d_in, const int* in_sizes, int n_in,
                              void* d_out, int out_size)
{
    const float* x    = (const float*)d_in[0];
    const float* Wqkv = (const float*)d_in[1];
    const float* bqkv = (const float*)d_in[2];
    const float* Wp   = (const float*)d_in[3];
    const float* bp   = (const float*)d_in[4];
    float* out = (float*)d_out;

    __half *qkv, *att, *xh, *wqkv_t, *wp_t;
    cudaGetSymbolAddress((void**)&qkv, g_qkv);
    cudaGetSymbolAddress((void**)&att, g_att);
    cudaGetSymbolAddress((void**)&xh, g_xh);
    cudaGetSymbolAddress((void**)&wqkv_t, g_wqkv_t);
    cudaGetSymbolAddress((void**)&wp_t, g_wp_t);

    cudaFuncSetAttribute(fa_kernel,
                         cudaFuncAttributeMaxDynamicSharedMemorySize, FA_SMEM_BYTES);
    cudaFuncSetAttribute(gemm_f16_kernel<1>,
                         cudaFuncAttributeMaxDynamicSharedMemorySize, GEMM_SMEM_BYTES);
    cudaFuncSetAttribute(gemm_f16_kernel<0>,
                         cudaFuncAttributeMaxDynamicSharedMemorySize, GEMM_SMEM_BYTES);

    // 0) fused prepass
    prepass_kernel<<<PRE_BLOCKS, 256>>>(x, xh, Wqkv, wqkv_t, Wp, wp_t);

    // 1) QKV = x @ Wqkv + b
    {
        dim3 grid(QKVN / GN, MROWS / GM);
        gemm_f16_kernel<1><<<grid, GT, GEMM_SMEM_BYTES>>>(xh, wqkv_t, bqkv, qkv,
                                                          MROWS, QKVN, DMODEL);
    }
    // 2) fused attention -> att (1024 CTAs, longest-first, 2 CTAs/SM)
    {
        dim3 grid(SEQ / 128, BH);
        fa_kernel<<<grid, 256, FA_SMEM_BYTES>>>(qkv, att);
    }
    // 3) out = att @ Wp + bp
    {
        dim3 grid(DMODEL / GN, MROWS / GM);
        gemm_f16_kernel<0><<<grid, GT, GEMM_SMEM_BYTES>>>(att, wp_t, bp, out,
                                                          MROWS, DMODEL, DMODEL);
    }
}